// round 13
// baseline (speedup 1.0000x reference)
#include <cuda_runtime.h>
#include <math.h>

// Shape (4, 2, 16, 512, 512) fp32
#define R       8                  // B*C channels
#define NS      4194304            // spatial elems per channel
#define NS4     (NS / 4)           // float4 per channel
#define NBINS   256
#define TPB     256
#define CHUNK   4                  // float4 per batch

#define BPC_MM  1024               // minmax: 1 batch/block
#define IT_H    4
#define BPC_H   256                // hist: 4 batches/block
#define IT_M    8
#define BPC_M   128                // main: 8 batches/block -> 1024 blocks, 1 wave

// ------------- scratch: static init == post-reset state --------------------
__device__ unsigned int g_minkey[R] = {0xFFFFFFFFu,0xFFFFFFFFu,0xFFFFFFFFu,0xFFFFFFFFu,
                                       0xFFFFFFFFu,0xFFFFFFFFu,0xFFFFFFFFu,0xFFFFFFFFu};
__device__ unsigned int       g_maxkey[R];          // 0
__device__ unsigned int       g_hist[R][NBINS];     // 0
__device__ float              g_bound[R][NBINS + 1];
__device__ float              g_thr[R];
__device__ double             g_msum[R], g_inter[R], g_ssum[R];
__device__ unsigned long long g_fg[R];
__device__ unsigned int       g_cnt_mm[R], g_cnt_hist[R], g_cnt_main;

__device__ __forceinline__ unsigned int fkey(float f) {
    unsigned int u = __float_as_uint(f);
    return (u & 0x80000000u) ? ~u : (u | 0x80000000u);
}
__device__ __forceinline__ float ikey(unsigned int k) {
    unsigned int u = (k & 0x80000000u) ? (k & 0x7FFFFFFFu) : ~k;
    return __uint_as_float(u);
}
__device__ __forceinline__ float bin_center(float lo, float span, int i) {
    float t0 = (float)i       * (1.0f / 256.0f);
    float t1 = (float)(i + 1) * (1.0f / 256.0f);
    float e0 = __fadd_rn(lo, __fmul_rn(span, t0));
    float e1 = __fadd_rn(lo, __fmul_rn(span, t1));
    return __fmul_rn(__fadd_rn(e0, e1), 0.5f);
}
// reference-exact bin of d = x - lo (d >= 0)
__device__ __forceinline__ int exact_bin(float d, float sspan) {
    float q = __fmul_rn(__fdiv_rn(d, sspan), 256.0f);
    int b = (int)q;                       // F2I trunc (saturating)
    return min(max(b, 0), NBINS - 1);
}

// ------- kernel 1: per-channel min/max + last block builds bound table -----
__global__ __launch_bounds__(TPB) void k_minmax(const float4* __restrict__ tgt) {
    const int c = blockIdx.y;
    const int tid = threadIdx.x;
    const float4* base = tgt + (size_t)c * NS4
                             + (size_t)blockIdx.x * (TPB * CHUNK) + tid;
    float4 V[CHUNK];
    #pragma unroll
    for (int k = 0; k < CHUNK; k++) V[k] = base[k * TPB];

    float lo0 = INFINITY, hi0 = -INFINITY, lo1 = INFINITY, hi1 = -INFINITY;
    #pragma unroll
    for (int k = 0; k < CHUNK; k++) {
        float l = fminf(fminf(V[k].x, V[k].y), fminf(V[k].z, V[k].w));
        float h = fmaxf(fmaxf(V[k].x, V[k].y), fmaxf(V[k].z, V[k].w));
        if (k & 1) { lo1 = fminf(lo1, l); hi1 = fmaxf(hi1, h); }
        else       { lo0 = fminf(lo0, l); hi0 = fmaxf(hi0, h); }
    }
    float lo = fminf(lo0, lo1), hi = fmaxf(hi0, hi1);
    for (int o = 16; o > 0; o >>= 1) {
        lo = fminf(lo, __shfl_down_sync(0xFFFFFFFFu, lo, o));
        hi = fmaxf(hi, __shfl_down_sync(0xFFFFFFFFu, hi, o));
    }
    __shared__ float slo[8], shi[8];
    int w = tid >> 5, lane = tid & 31;
    if (lane == 0) { slo[w] = lo; shi[w] = hi; }
    __syncthreads();
    if (tid == 0) {
        float l = slo[0], h = shi[0];
        for (int i = 1; i < 8; i++) { l = fminf(l, slo[i]); h = fmaxf(h, shi[i]); }
        atomicMin(&g_minkey[c], fkey(l));
        atomicMax(&g_maxkey[c], fkey(h));
    }

    // ---- last block of this channel: exact-bin boundary table -------------
    __threadfence();
    __shared__ bool is_last;
    if (tid == 0)
        is_last = (atomicAdd(&g_cnt_mm[c], 1u) == (unsigned)(BPC_MM - 1));
    __syncthreads();
    if (!is_last) return;

    float clo  = ikey(__ldcg(&g_minkey[c]));
    float chi  = ikey(__ldcg(&g_maxkey[c]));
    float span = __fsub_rn(chi, clo);
    float sspan = (span > 0.0f) ? span : 1.0f;

    if (tid == 0) {
        g_bound[c][0]     = -INFINITY;
        g_bound[c][NBINS] =  INFINITY;
    } else {
        // minimal nonneg float d with exact_bin(d) >= tid (monotone in bits)
        unsigned loU = 0u, hiU = 0x7F800000u;
        while (loU < hiU) {
            unsigned mid = (loU + hiU) >> 1;
            if (exact_bin(__uint_as_float(mid), sspan) >= tid) hiU = mid;
            else loU = mid + 1u;
        }
        g_bound[c][tid] = __uint_as_float(loU);
    }
}

// -------- kernel 2: histogram (div-free exact binning) + fused Otsu --------
__global__ __launch_bounds__(TPB) void k_hist(const float4* __restrict__ tgt) {
    const int c = blockIdx.y;
    __shared__ unsigned int sh[8][NBINS];   // per-warp sub-histograms
    __shared__ float s_bound[NBINS + 1];
    __shared__ float s_lo, s_inv, s_span_raw;
    int tid = threadIdx.x, w = tid >> 5;
    for (int i = tid; i < 8 * NBINS; i += TPB)
        ((unsigned int*)sh)[i] = 0u;
    s_bound[tid] = g_bound[c][tid];
    if (tid == 0) {
        s_bound[NBINS] = g_bound[c][NBINS];
        float lo = ikey(g_minkey[c]);
        float hi = ikey(g_maxkey[c]);
        float span = __fsub_rn(hi, lo);
        s_span_raw = span;
        s_lo = lo;
        s_inv = __fdiv_rn(256.0f, (span > 0.0f) ? span : 1.0f);
    }
    __syncthreads();
    const float lo = s_lo, inv = s_inv;

    const float4* rtop = tgt + (size_t)c * NS4 + (NS4 - 1);
    const int bbase = blockIdx.x * (TPB * CHUNK * IT_H) + tid;
    #pragma unroll
    for (int it = 0; it < IT_H; it++) {
        float4 V[CHUNK];
        const int ibase = bbase + it * (TPB * CHUNK);
        #pragma unroll
        for (int k = 0; k < CHUNK; k++)        // 4 LDG.128 back-to-back
            V[k] = rtop[-(ibase + k * TPB)];
        #pragma unroll
        for (int k = 0; k < CHUNK; k++) {
            #pragma unroll
            for (int j = 0; j < 4; j++) {
                float x = (j == 0) ? V[k].x : (j == 1) ? V[k].y
                        : (j == 2) ? V[k].z : V[k].w;
                float d = __fsub_rn(x, lo);
                int b0 = (int)__fmul_rn(d, inv);          // 1 FMUL approx
                b0 = min(max(b0, 0), NBINS - 1);
                // branchless +-1 exact fixup (|approx-exact| < 1 bin)
                int b = b0 + (d >= s_bound[b0 + 1] ? 1 : 0)
                           - (d <  s_bound[b0]     ? 1 : 0);
                atomicAdd(&sh[w][b], 1u);
            }
        }
    }
    __syncthreads();
    {
        unsigned int s = 0;
        #pragma unroll
        for (int k = 0; k < 8; k++) s += sh[k][tid];
        if (s) atomicAdd(&g_hist[c][tid], s);
    }

    // ---- last block of this channel computes the Otsu threshold ----
    __threadfence();
    __shared__ bool is_last;
    if (tid == 0)
        is_last = (atomicAdd(&g_cnt_hist[c], 1u) == (unsigned)(BPC_H - 1));
    __syncthreads();
    if (!is_last) return;

    __shared__ float s_h[NBINS], s_hm[NBINS], s_ctr[NBINS];
    __shared__ float s_cs[NBINS], s_cm[NBINS];
    __shared__ float rv[NBINS]; __shared__ int ri[NBINS];

    const float span_raw = s_span_raw;
    float h   = (float)__ldcg(&g_hist[c][tid]);
    float ctr = bin_center(lo, span_raw, tid);
    s_h[tid] = h; s_ctr[tid] = ctr; s_hm[tid] = __fmul_rn(h, ctr);
    __syncthreads();

    if (tid == 0) {   // sequential fp32 cumsum (matches reference order)
        float cs = 0.0f, cm = 0.0f;
        #pragma unroll
        for (int i = 0; i < NBINS; i++) {
            cs = __fadd_rn(cs, s_h[i]);
            cm = __fadd_rn(cm, s_hm[i]);
            s_cs[i] = cs; s_cm[i] = cm;
        }
    }
    __syncthreads();
    const float total = s_cs[NBINS - 1];
    const float gmean = s_cm[NBINS - 1];

    float cs = s_cs[tid], cm = s_cm[tid];
    float A  = __fsub_rn(__fmul_rn(cm, total), __fmul_rn(gmean, cs));
    float dn = __fadd_rn(__fmul_rn(cs, __fsub_rn(total, cs)), 1e-10f);
    float iv = __fdiv_rn(__fmul_rn(A, A), dn);

    rv[tid] = iv; ri[tid] = tid;
    __syncthreads();
    for (int s = NBINS / 2; s > 0; s >>= 1) {   // argmax, first-index tie-break
        if (tid < s) {
            if (rv[tid + s] > rv[tid] ||
                (rv[tid + s] == rv[tid] && ri[tid + s] < ri[tid])) {
                rv[tid] = rv[tid + s]; ri[tid] = ri[tid + s];
            }
        }
        __syncthreads();
    }
    if (tid == 0)
        g_thr[c] = (span_raw > 0.0f) ? s_ctr[ri[0]] : lo;
}

// ---- kernel 3: fused main reductions (R12, unchanged) ---------------------
__global__ __launch_bounds__(TPB, 7) void k_main(const float4* __restrict__ pred,
                                                 const float4* __restrict__ tgt,
                                                 float* __restrict__ out) {
    const int c = blockIdx.y;
    const int tid = threadIdx.x;
    const float thr = g_thr[c];
    const size_t base = (size_t)c * NS4
                      + (size_t)blockIdx.x * (TPB * CHUNK * IT_M) + tid;
    const float4* pb = pred + base;
    const float4* tb = tgt  + base;

    float msum0 = 0.f, int0 = 0.f, ss0 = 0.f;
    float msum1 = 0.f, int1 = 0.f, ss1 = 0.f;
    int fg = 0;

    #pragma unroll
    for (int it = 0; it < IT_M; it++) {
        float4 P[CHUNK], T[CHUNK];
        const int ioff = it * (TPB * CHUNK);
        #pragma unroll
        for (int k = 0; k < CHUNK; k++) {     // 8 LDG.128 back-to-back (MLP 8)
            P[k] = pb[ioff + k * TPB];
            T[k] = tb[ioff + k * TPB];
        }
        #pragma unroll
        for (int k = 0; k < CHUNK; k++) {
            #pragma unroll
            for (int j = 0; j < 4; j++) {
                float p = (j == 0) ? P[k].x : (j == 1) ? P[k].y
                        : (j == 2) ? P[k].z : P[k].w;
                float t = (j == 0) ? T[k].x : (j == 1) ? T[k].y
                        : (j == 2) ? T[k].z : T[k].w;
                bool m = (t >= thr);
                float d  = p - t;
                float se = d * d;
                float ax  = fabsf(p);
                float num = p - (-0.95f) * p;                 // 1.95*x
                float den = (-0.95f - (-1.9f) * ax) + 1.0f;   // 0.05 + 1.9|x|
                float sp  = __saturatef(__fdividef(num, den));
                float sem = m ? se : 0.0f;
                float spm = m ? sp : 0.0f;
                fg += m;
                if (k & 1) { msum1 += sem; ss1 += sp; int1 += spm; }
                else       { msum0 += sem; ss0 += sp; int0 += spm; }
            }
        }
    }
    float msum = msum0 + msum1;
    float inter = int0 + int1,  ssum = ss0 + ss1;

    for (int o = 16; o > 0; o >>= 1) {
        msum  += __shfl_down_sync(0xFFFFFFFFu, msum,  o);
        inter += __shfl_down_sync(0xFFFFFFFFu, inter, o);
        ssum  += __shfl_down_sync(0xFFFFFFFFu, ssum,  o);
        fg    += __shfl_down_sync(0xFFFFFFFFu, fg,    o);
    }
    __shared__ float  s0[8], s2[8], s3[8];
    __shared__ int    s4[8];
    int w = tid >> 5, lane = tid & 31;
    if (lane == 0) { s0[w]=msum; s2[w]=inter; s3[w]=ssum; s4[w]=fg; }
    __syncthreads();
    __shared__ bool is_last;
    if (tid == 0) {
        double a=0, cI=0, dS=0; long long f=0;
        #pragma unroll
        for (int k = 0; k < 8; k++) { a+=s0[k]; cI+=s2[k]; dS+=s3[k]; f+=s4[k]; }
        atomicAdd(&g_msum[c],  a);
        atomicAdd(&g_inter[c], cI);
        atomicAdd(&g_ssum[c],  dS);
        atomicAdd(&g_fg[c], (unsigned long long)f);
        __threadfence();
        is_last = (atomicAdd(&g_cnt_main, 1u) == (unsigned)(BPC_M * R - 1));
    }
    __syncthreads();
    if (!is_last) return;

    // ---- globally-last block: combine to scalar ----
    if (tid == 0) {
        double mse_sum = 0.0, dice_sum = 0.0;
        int nmask = 0;
        for (int ch = 0; ch < R; ch++) {
            double fgc = (double)__ldcg(&g_fg[ch]);
            // fg >= 1 always (thr is a bin center strictly below channel max)
            mse_sum += __ldcg(&g_msum[ch]) / (fgc + 1e-6);
            dice_sum += 1.0 - 2.0 * __ldcg(&g_inter[ch]) /
                                    (__ldcg(&g_ssum[ch]) + fgc + 1e-6);
            nmask++;
        }
        double masked_mse = mse_sum / (double)R;
        double dice = (nmask > 0) ? dice_sum / (double)nmask : 0.0;
        out[0] = (float)(0.5 * masked_mse + 0.5 * dice);
    }
    __syncthreads();   // combine reads done before reset below

    // ---- self-clean scratch back to static-init state for next replay ----
    for (int i = tid; i < R * NBINS; i += TPB)
        ((unsigned int*)g_hist)[i] = 0u;
    if (tid < R) {
        g_minkey[tid] = 0xFFFFFFFFu;
        g_maxkey[tid] = 0u;
        g_msum[tid] = 0.0; g_inter[tid] = 0.0; g_ssum[tid] = 0.0;
        g_fg[tid] = 0ull;
        g_thr[tid] = 0.0f;
        g_cnt_mm[tid] = 0u;
        g_cnt_hist[tid] = 0u;
    }
    if (tid == R) g_cnt_main = 0u;
}

// ---------------- launch ----------------
extern "C" void kernel_launch(void* const* d_in, const int* in_sizes, int n_in,
                              void* d_out, int out_size) {
    const float4* pred = (const float4*)d_in[0];
    const float4* tgt  = (const float4*)d_in[1];
    float* out = (float*)d_out;

    k_minmax<<<dim3(BPC_MM, R), TPB>>>(tgt);
    k_hist  <<<dim3(BPC_H,  R), TPB>>>(tgt);
    k_main  <<<dim3(BPC_M,  R), TPB>>>(pred, tgt, out);
}

// round 14
// speedup vs baseline: 1.0406x; 1.0406x over previous
#include <cuda_runtime.h>
#include <math.h>

// Shape (4, 2, 16, 512, 512) fp32
#define R       8                  // B*C channels
#define NS      4194304            // spatial elems per channel
#define NS4     (NS / 4)           // float4 per channel
#define NBINS   256
#define TPB     256
#define CHUNK   4                  // float4 per batch

#define BPC_MM  1024               // minmax: 1 batch/block (measured-good)
#define IT_H    4
#define BPC_H   256                // hist: 4 batches/block (measured-good)
#define IT_M    16
#define BPC_M   64                 // main: 16 batches/block -> 512 blocks, 1 wave

// ------------- scratch: static init == post-reset state --------------------
__device__ unsigned int g_minkey[R] = {0xFFFFFFFFu,0xFFFFFFFFu,0xFFFFFFFFu,0xFFFFFFFFu,
                                       0xFFFFFFFFu,0xFFFFFFFFu,0xFFFFFFFFu,0xFFFFFFFFu};
__device__ unsigned int       g_maxkey[R];          // 0
__device__ unsigned int       g_hist[R][NBINS];     // 0
__device__ float              g_thr[R];
__device__ double             g_msum[R], g_inter[R], g_ssum[R];
__device__ unsigned long long g_fg[R];
__device__ unsigned int       g_cnt_hist[R], g_cnt_main;

__device__ __forceinline__ unsigned int fkey(float f) {
    unsigned int u = __float_as_uint(f);
    return (u & 0x80000000u) ? ~u : (u | 0x80000000u);
}
__device__ __forceinline__ float ikey(unsigned int k) {
    unsigned int u = (k & 0x80000000u) ? (k & 0x7FFFFFFFu) : ~k;
    return __uint_as_float(u);
}
__device__ __forceinline__ float bin_center(float lo, float span, int i) {
    float t0 = (float)i       * (1.0f / 256.0f);
    float t1 = (float)(i + 1) * (1.0f / 256.0f);
    float e0 = __fadd_rn(lo, __fmul_rn(span, t0));
    float e1 = __fadd_rn(lo, __fmul_rn(span, t1));
    return __fmul_rn(__fadd_rn(e0, e1), 0.5f);
}

// ---------------- kernel 1: per-channel min/max (R12, unchanged) -----------
__global__ __launch_bounds__(TPB) void k_minmax(const float4* __restrict__ tgt) {
    const int c = blockIdx.y;
    const int tid = threadIdx.x;
    const float4* base = tgt + (size_t)c * NS4
                             + (size_t)blockIdx.x * (TPB * CHUNK) + tid;
    float4 V[CHUNK];
    #pragma unroll
    for (int k = 0; k < CHUNK; k++) V[k] = base[k * TPB];

    float lo0 = INFINITY, hi0 = -INFINITY, lo1 = INFINITY, hi1 = -INFINITY;
    #pragma unroll
    for (int k = 0; k < CHUNK; k++) {
        float l = fminf(fminf(V[k].x, V[k].y), fminf(V[k].z, V[k].w));
        float h = fmaxf(fmaxf(V[k].x, V[k].y), fmaxf(V[k].z, V[k].w));
        if (k & 1) { lo1 = fminf(lo1, l); hi1 = fmaxf(hi1, h); }
        else       { lo0 = fminf(lo0, l); hi0 = fmaxf(hi0, h); }
    }
    float lo = fminf(lo0, lo1), hi = fmaxf(hi0, hi1);
    for (int o = 16; o > 0; o >>= 1) {
        lo = fminf(lo, __shfl_down_sync(0xFFFFFFFFu, lo, o));
        hi = fmaxf(hi, __shfl_down_sync(0xFFFFFFFFu, hi, o));
    }
    __shared__ float slo[8], shi[8];
    int w = tid >> 5, lane = tid & 31;
    if (lane == 0) { slo[w] = lo; shi[w] = hi; }
    __syncthreads();
    if (tid == 0) {
        float l = slo[0], h = shi[0];
        for (int i = 1; i < 8; i++) { l = fminf(l, slo[i]); h = fmaxf(h, shi[i]); }
        atomicMin(&g_minkey[c], fkey(l));
        atomicMax(&g_maxkey[c], fkey(h));
    }
}

// -------- kernel 2: histogram (R12 exact-division) + fused Otsu ------------
__global__ __launch_bounds__(TPB) void k_hist(const float4* __restrict__ tgt) {
    const int c = blockIdx.y;
    __shared__ unsigned int sh[8][NBINS];   // per-warp sub-histograms
    __shared__ float s_lo, s_span_safe, s_span_raw;
    int tid = threadIdx.x, w = tid >> 5;
    for (int i = tid; i < 8 * NBINS; i += TPB)
        ((unsigned int*)sh)[i] = 0u;
    if (tid == 0) {
        float lo = ikey(g_minkey[c]);
        float hi = ikey(g_maxkey[c]);
        float span = __fsub_rn(hi, lo);
        s_lo = lo;
        s_span_raw = span;
        s_span_safe = (span > 0.0f) ? span : 1.0f;
    }
    __syncthreads();
    const float lo = s_lo, span = s_span_safe;

    const float4* rtop = tgt + (size_t)c * NS4 + (NS4 - 1);
    const int bbase = blockIdx.x * (TPB * CHUNK * IT_H) + tid;
    #pragma unroll
    for (int it = 0; it < IT_H; it++) {
        float4 V[CHUNK];
        const int ibase = bbase + it * (TPB * CHUNK);
        #pragma unroll
        for (int k = 0; k < CHUNK; k++)        // 4 LDG.128 back-to-back
            V[k] = rtop[-(ibase + k * TPB)];
        #pragma unroll
        for (int k = 0; k < CHUNK; k++) {
            #pragma unroll
            for (int j = 0; j < 4; j++) {
                float x = (j == 0) ? V[k].x : (j == 1) ? V[k].y
                        : (j == 2) ? V[k].z : V[k].w;
                float q = __fmul_rn(__fdiv_rn(__fsub_rn(x, lo), span), 256.0f);
                int b = (int)q;
                b = min(max(b, 0), NBINS - 1);
                atomicAdd(&sh[w][b], 1u);
            }
        }
    }
    __syncthreads();
    {
        unsigned int s = 0;
        #pragma unroll
        for (int k = 0; k < 8; k++) s += sh[k][tid];
        if (s) atomicAdd(&g_hist[c][tid], s);
    }

    // ---- last block of this channel computes the Otsu threshold ----
    __threadfence();
    __shared__ bool is_last;
    if (tid == 0)
        is_last = (atomicAdd(&g_cnt_hist[c], 1u) == (unsigned)(BPC_H - 1));
    __syncthreads();
    if (!is_last) return;

    __shared__ float s_h[NBINS], s_hm[NBINS], s_ctr[NBINS];
    __shared__ float s_cs[NBINS], s_cm[NBINS];
    __shared__ float rv[NBINS]; __shared__ int ri[NBINS];

    const float span_raw = s_span_raw;
    float h   = (float)__ldcg(&g_hist[c][tid]);
    float ctr = bin_center(lo, span_raw, tid);
    s_h[tid] = h; s_ctr[tid] = ctr; s_hm[tid] = __fmul_rn(h, ctr);
    __syncthreads();

    if (tid == 0) {   // sequential fp32 cumsum (matches reference order)
        float cs = 0.0f, cm = 0.0f;
        #pragma unroll
        for (int i = 0; i < NBINS; i++) {
            cs = __fadd_rn(cs, s_h[i]);
            cm = __fadd_rn(cm, s_hm[i]);
            s_cs[i] = cs; s_cm[i] = cm;
        }
    }
    __syncthreads();
    const float total = s_cs[NBINS - 1];
    const float gmean = s_cm[NBINS - 1];

    float cs = s_cs[tid], cm = s_cm[tid];
    float A  = __fsub_rn(__fmul_rn(cm, total), __fmul_rn(gmean, cs));
    float dn = __fadd_rn(__fmul_rn(cs, __fsub_rn(total, cs)), 1e-10f);
    float iv = __fdiv_rn(__fmul_rn(A, A), dn);

    rv[tid] = iv; ri[tid] = tid;
    __syncthreads();
    for (int s = NBINS / 2; s > 0; s >>= 1) {   // argmax, first-index tie-break
        if (tid < s) {
            if (rv[tid + s] > rv[tid] ||
                (rv[tid + s] == rv[tid] && ri[tid + s] < ri[tid])) {
                rv[tid] = rv[tid + s]; ri[tid] = ri[tid + s];
            }
        }
        __syncthreads();
    }
    if (tid == 0)
        g_thr[c] = (span_raw > 0.0f) ? s_ctr[ri[0]] : lo;
}

// ---- kernel 3: fused main reductions (16 iters/block, 512 blocks) ---------
__global__ __launch_bounds__(TPB, 7) void k_main(const float4* __restrict__ pred,
                                                 const float4* __restrict__ tgt,
                                                 float* __restrict__ out) {
    const int c = blockIdx.y;
    const int tid = threadIdx.x;
    const float thr = g_thr[c];
    const size_t base = (size_t)c * NS4
                      + (size_t)blockIdx.x * (TPB * CHUNK * IT_M) + tid;
    const float4* pb = pred + base;
    const float4* tb = tgt  + base;

    float msum0 = 0.f, int0 = 0.f, ss0 = 0.f;
    float msum1 = 0.f, int1 = 0.f, ss1 = 0.f;
    int fg = 0;

    #pragma unroll
    for (int it = 0; it < IT_M; it++) {
        float4 P[CHUNK], T[CHUNK];
        const int ioff = it * (TPB * CHUNK);
        #pragma unroll
        for (int k = 0; k < CHUNK; k++) {     // 8 LDG.128 back-to-back (MLP 8)
            P[k] = pb[ioff + k * TPB];
            T[k] = tb[ioff + k * TPB];
        }
        #pragma unroll
        for (int k = 0; k < CHUNK; k++) {
            #pragma unroll
            for (int j = 0; j < 4; j++) {
                float p = (j == 0) ? P[k].x : (j == 1) ? P[k].y
                        : (j == 2) ? P[k].z : P[k].w;
                float t = (j == 0) ? T[k].x : (j == 1) ? T[k].y
                        : (j == 2) ? T[k].z : T[k].w;
                bool m = (t >= thr);
                float d  = p - t;
                float se = d * d;
                float ax  = fabsf(p);
                float num = p - (-0.95f) * p;                 // 1.95*x
                float den = (-0.95f - (-1.9f) * ax) + 1.0f;   // 0.05 + 1.9|x|
                float sp  = __saturatef(__fdividef(num, den));
                float sem = m ? se : 0.0f;
                float spm = m ? sp : 0.0f;
                fg += m;
                if (k & 1) { msum1 += sem; ss1 += sp; int1 += spm; }
                else       { msum0 += sem; ss0 += sp; int0 += spm; }
            }
        }
    }
    float msum = msum0 + msum1;
    float inter = int0 + int1,  ssum = ss0 + ss1;

    for (int o = 16; o > 0; o >>= 1) {
        msum  += __shfl_down_sync(0xFFFFFFFFu, msum,  o);
        inter += __shfl_down_sync(0xFFFFFFFFu, inter, o);
        ssum  += __shfl_down_sync(0xFFFFFFFFu, ssum,  o);
        fg    += __shfl_down_sync(0xFFFFFFFFu, fg,    o);
    }
    __shared__ float  s0[8], s2[8], s3[8];
    __shared__ int    s4[8];
    int w = tid >> 5, lane = tid & 31;
    if (lane == 0) { s0[w]=msum; s2[w]=inter; s3[w]=ssum; s4[w]=fg; }
    __syncthreads();
    __shared__ bool is_last;
    if (tid == 0) {
        double a=0, cI=0, dS=0; long long f=0;
        #pragma unroll
        for (int k = 0; k < 8; k++) { a+=s0[k]; cI+=s2[k]; dS+=s3[k]; f+=s4[k]; }
        atomicAdd(&g_msum[c],  a);
        atomicAdd(&g_inter[c], cI);
        atomicAdd(&g_ssum[c],  dS);
        atomicAdd(&g_fg[c], (unsigned long long)f);
        __threadfence();
        is_last = (atomicAdd(&g_cnt_main, 1u) == (unsigned)(BPC_M * R - 1));
    }
    __syncthreads();
    if (!is_last) return;

    // ---- globally-last block: combine to scalar ----
    if (tid == 0) {
        double mse_sum = 0.0, dice_sum = 0.0;
        int nmask = 0;
        for (int ch = 0; ch < R; ch++) {
            double fgc = (double)__ldcg(&g_fg[ch]);
            // fg >= 1 always (thr is a bin center strictly below channel max)
            mse_sum += __ldcg(&g_msum[ch]) / (fgc + 1e-6);
            dice_sum += 1.0 - 2.0 * __ldcg(&g_inter[ch]) /
                                    (__ldcg(&g_ssum[ch]) + fgc + 1e-6);
            nmask++;
        }
        double masked_mse = mse_sum / (double)R;
        double dice = (nmask > 0) ? dice_sum / (double)nmask : 0.0;
        out[0] = (float)(0.5 * masked_mse + 0.5 * dice);
    }
    __syncthreads();   // combine reads done before reset below

    // ---- self-clean scratch back to static-init state for next replay ----
    for (int i = tid; i < R * NBINS; i += TPB)
        ((unsigned int*)g_hist)[i] = 0u;
    if (tid < R) {
        g_minkey[tid] = 0xFFFFFFFFu;
        g_maxkey[tid] = 0u;
        g_msum[tid] = 0.0; g_inter[tid] = 0.0; g_ssum[tid] = 0.0;
        g_fg[tid] = 0ull;
        g_thr[tid] = 0.0f;
        g_cnt_hist[tid] = 0u;
    }
    if (tid == R) g_cnt_main = 0u;
}

// ---------------- launch ----------------
extern "C" void kernel_launch(void* const* d_in, const int* in_sizes, int n_in,
                              void* d_out, int out_size) {
    const float4* pred = (const float4*)d_in[0];
    const float4* tgt  = (const float4*)d_in[1];
    float* out = (float*)d_out;

    k_minmax<<<dim3(BPC_MM, R), TPB>>>(tgt);
    k_hist  <<<dim3(BPC_H,  R), TPB>>>(tgt);
    k_main  <<<dim3(BPC_M,  R), TPB>>>(pred, tgt, out);
}

// round 15
// speedup vs baseline: 1.1446x; 1.0999x over previous
#include <cuda_runtime.h>
#include <math.h>

// Shape (4, 2, 16, 512, 512) fp32
#define R       8                  // B*C channels
#define NS      4194304            // spatial elems per channel
#define NS4     (NS / 4)           // float4 per channel
#define NBINS   256
#define TPB     256
#define CHUNK   4                  // float4 per batch

// measured-optimal shapes (R12)
#define BPC_MM  1024               // minmax: 1 batch/block, 8192 blocks
#define IT_H    4
#define BPC_H   256                // hist: 4 batches/block, 2048 blocks
#define IT_M    8
#define BPC_M   128                // main: 8 batches/block, 1024 blocks, 1 wave

// ------------- scratch: static init == post-reset state --------------------
__device__ unsigned int g_minkey[R] = {0xFFFFFFFFu,0xFFFFFFFFu,0xFFFFFFFFu,0xFFFFFFFFu,
                                       0xFFFFFFFFu,0xFFFFFFFFu,0xFFFFFFFFu,0xFFFFFFFFu};
__device__ unsigned int       g_maxkey[R];          // 0
__device__ unsigned int       g_hist[R][NBINS];     // 0
__device__ float              g_thr[R];
__device__ double             g_msum[R], g_inter[R], g_ssum[R];
__device__ unsigned long long g_fg[R];
__device__ unsigned int       g_cnt_hist[R], g_cnt_main;

__device__ __forceinline__ unsigned int fkey(float f) {
    unsigned int u = __float_as_uint(f);
    return (u & 0x80000000u) ? ~u : (u | 0x80000000u);
}
__device__ __forceinline__ float ikey(unsigned int k) {
    unsigned int u = (k & 0x80000000u) ? (k & 0x7FFFFFFFu) : ~k;
    return __uint_as_float(u);
}
__device__ __forceinline__ float bin_center(float lo, float span, int i) {
    float t0 = (float)i       * (1.0f / 256.0f);
    float t1 = (float)(i + 1) * (1.0f / 256.0f);
    float e0 = __fadd_rn(lo, __fmul_rn(span, t0));
    float e1 = __fadd_rn(lo, __fmul_rn(span, t1));
    return __fmul_rn(__fadd_rn(e0, e1), 0.5f);
}

// ---------------- kernel 1: per-channel min/max ----------------------------
__global__ __launch_bounds__(TPB) void k_minmax(const float4* __restrict__ tgt) {
    const int c = blockIdx.y;
    const int tid = threadIdx.x;
    const float4* base = tgt + (size_t)c * NS4
                             + (size_t)blockIdx.x * (TPB * CHUNK) + tid;
    float4 V[CHUNK];
    #pragma unroll
    for (int k = 0; k < CHUNK; k++) V[k] = base[k * TPB];

    float lo0 = INFINITY, hi0 = -INFINITY, lo1 = INFINITY, hi1 = -INFINITY;
    #pragma unroll
    for (int k = 0; k < CHUNK; k++) {
        float l = fminf(fminf(V[k].x, V[k].y), fminf(V[k].z, V[k].w));
        float h = fmaxf(fmaxf(V[k].x, V[k].y), fmaxf(V[k].z, V[k].w));
        if (k & 1) { lo1 = fminf(lo1, l); hi1 = fmaxf(hi1, h); }
        else       { lo0 = fminf(lo0, l); hi0 = fmaxf(hi0, h); }
    }
    float lo = fminf(lo0, lo1), hi = fmaxf(hi0, hi1);
    for (int o = 16; o > 0; o >>= 1) {
        lo = fminf(lo, __shfl_down_sync(0xFFFFFFFFu, lo, o));
        hi = fmaxf(hi, __shfl_down_sync(0xFFFFFFFFu, hi, o));
    }
    __shared__ float slo[8], shi[8];
    int w = tid >> 5, lane = tid & 31;
    if (lane == 0) { slo[w] = lo; shi[w] = hi; }
    __syncthreads();
    if (tid == 0) {
        float l = slo[0], h = shi[0];
        for (int i = 1; i < 8; i++) { l = fminf(l, slo[i]); h = fmaxf(h, shi[i]); }
        atomicMin(&g_minkey[c], fkey(l));
        atomicMax(&g_maxkey[c], fkey(h));
    }
}

// -------- kernel 2: histogram (exact-division) + fused Otsu ----------------
__global__ __launch_bounds__(TPB) void k_hist(const float4* __restrict__ tgt) {
    const int c = blockIdx.y;
    __shared__ unsigned int sh[8][NBINS];   // per-warp sub-histograms
    __shared__ float s_lo, s_span_safe, s_span_raw;
    int tid = threadIdx.x, w = tid >> 5;
    for (int i = tid; i < 8 * NBINS; i += TPB)
        ((unsigned int*)sh)[i] = 0u;
    if (tid == 0) {
        float lo = ikey(g_minkey[c]);
        float hi = ikey(g_maxkey[c]);
        float span = __fsub_rn(hi, lo);
        s_lo = lo;
        s_span_raw = span;
        s_span_safe = (span > 0.0f) ? span : 1.0f;
    }
    __syncthreads();
    const float lo = s_lo, span = s_span_safe;

    const float4* rtop = tgt + (size_t)c * NS4 + (NS4 - 1);
    const int bbase = blockIdx.x * (TPB * CHUNK * IT_H) + tid;
    #pragma unroll
    for (int it = 0; it < IT_H; it++) {
        float4 V[CHUNK];
        const int ibase = bbase + it * (TPB * CHUNK);
        #pragma unroll
        for (int k = 0; k < CHUNK; k++)        // 4 LDG.128 back-to-back
            V[k] = rtop[-(ibase + k * TPB)];
        #pragma unroll
        for (int k = 0; k < CHUNK; k++) {
            #pragma unroll
            for (int j = 0; j < 4; j++) {
                float x = (j == 0) ? V[k].x : (j == 1) ? V[k].y
                        : (j == 2) ? V[k].z : V[k].w;
                float q = __fmul_rn(__fdiv_rn(__fsub_rn(x, lo), span), 256.0f);
                int b = (int)q;
                b = min(max(b, 0), NBINS - 1);
                atomicAdd(&sh[w][b], 1u);
            }
        }
    }
    __syncthreads();
    {
        unsigned int s = 0;
        #pragma unroll
        for (int k = 0; k < 8; k++) s += sh[k][tid];
        if (s) atomicAdd(&g_hist[c][tid], s);
    }

    // ---- last block of this channel computes the Otsu threshold ----
    __threadfence();
    __shared__ bool is_last;
    if (tid == 0)
        is_last = (atomicAdd(&g_cnt_hist[c], 1u) == (unsigned)(BPC_H - 1));
    __syncthreads();
    if (!is_last) return;

    __shared__ float s_h[NBINS], s_hm[NBINS], s_ctr[NBINS];
    __shared__ float s_cs[NBINS], s_cm[NBINS];
    __shared__ float rv[NBINS]; __shared__ int ri[NBINS];

    const float span_raw = s_span_raw;
    float h   = (float)__ldcg(&g_hist[c][tid]);
    float ctr = bin_center(lo, span_raw, tid);
    s_h[tid] = h; s_ctr[tid] = ctr; s_hm[tid] = __fmul_rn(h, ctr);
    __syncthreads();

    if (tid == 0) {   // sequential fp32 cumsum (matches reference order)
        float cs = 0.0f, cm = 0.0f;
        #pragma unroll
        for (int i = 0; i < NBINS; i++) {
            cs = __fadd_rn(cs, s_h[i]);
            cm = __fadd_rn(cm, s_hm[i]);
            s_cs[i] = cs; s_cm[i] = cm;
        }
    }
    __syncthreads();
    const float total = s_cs[NBINS - 1];
    const float gmean = s_cm[NBINS - 1];

    float cs = s_cs[tid], cm = s_cm[tid];
    float A  = __fsub_rn(__fmul_rn(cm, total), __fmul_rn(gmean, cs));
    float dn = __fadd_rn(__fmul_rn(cs, __fsub_rn(total, cs)), 1e-10f);
    float iv = __fdiv_rn(__fmul_rn(A, A), dn);

    rv[tid] = iv; ri[tid] = tid;
    __syncthreads();
    for (int s = NBINS / 2; s > 0; s >>= 1) {   // argmax, first-index tie-break
        if (tid < s) {
            if (rv[tid + s] > rv[tid] ||
                (rv[tid + s] == rv[tid] && ri[tid + s] < ri[tid])) {
                rv[tid] = rv[tid + s]; ri[tid] = ri[tid + s];
            }
        }
        __syncthreads();
    }
    if (tid == 0)
        g_thr[c] = (span_raw > 0.0f) ? s_ctr[ri[0]] : lo;
}

// ---- kernel 3: fused main reductions (1024 blocks, 1 wave) ----------------
__global__ __launch_bounds__(TPB, 7) void k_main(const float4* __restrict__ pred,
                                                 const float4* __restrict__ tgt,
                                                 float* __restrict__ out) {
    const int c = blockIdx.y;
    const int tid = threadIdx.x;
    const float thr = g_thr[c];
    const size_t base = (size_t)c * NS4
                      + (size_t)blockIdx.x * (TPB * CHUNK * IT_M) + tid;
    const float4* pb = pred + base;
    const float4* tb = tgt  + base;

    float msum0 = 0.f, int0 = 0.f, ss0 = 0.f;
    float msum1 = 0.f, int1 = 0.f, ss1 = 0.f;
    int fg = 0;

    #pragma unroll
    for (int it = 0; it < IT_M; it++) {
        float4 P[CHUNK], T[CHUNK];
        const int ioff = it * (TPB * CHUNK);
        #pragma unroll
        for (int k = 0; k < CHUNK; k++) {     // 8 LDG.128 back-to-back (MLP 8)
            P[k] = pb[ioff + k * TPB];
            T[k] = tb[ioff + k * TPB];
        }
        #pragma unroll
        for (int k = 0; k < CHUNK; k++) {
            #pragma unroll
            for (int j = 0; j < 4; j++) {
                float p = (j == 0) ? P[k].x : (j == 1) ? P[k].y
                        : (j == 2) ? P[k].z : P[k].w;
                float t = (j == 0) ? T[k].x : (j == 1) ? T[k].y
                        : (j == 2) ? T[k].z : T[k].w;
                bool m = (t >= thr);
                float d  = p - t;
                float se = d * d;
                // tunable sigmoid, k=-0.95, constants folded:
                // raw = 1.95*p / (0.05 + 1.9*|p|)
                float num = 1.95f * p;
                float den = __fmaf_rn(1.9f, fabsf(p), 0.05f);
                float sp  = __saturatef(__fdividef(num, den));
                float sem = m ? se : 0.0f;
                float spm = m ? sp : 0.0f;
                fg += m;
                if (k & 1) { msum1 += sem; ss1 += sp; int1 += spm; }
                else       { msum0 += sem; ss0 += sp; int0 += spm; }
            }
        }
    }
    float msum = msum0 + msum1;
    float inter = int0 + int1,  ssum = ss0 + ss1;

    for (int o = 16; o > 0; o >>= 1) {
        msum  += __shfl_down_sync(0xFFFFFFFFu, msum,  o);
        inter += __shfl_down_sync(0xFFFFFFFFu, inter, o);
        ssum  += __shfl_down_sync(0xFFFFFFFFu, ssum,  o);
        fg    += __shfl_down_sync(0xFFFFFFFFu, fg,    o);
    }
    __shared__ float  s0[8], s2[8], s3[8];
    __shared__ int    s4[8];
    int w = tid >> 5, lane = tid & 31;
    if (lane == 0) { s0[w]=msum; s2[w]=inter; s3[w]=ssum; s4[w]=fg; }
    __syncthreads();
    __shared__ bool is_last;
    if (tid == 0) {
        double a=0, cI=0, dS=0; long long f=0;
        #pragma unroll
        for (int k = 0; k < 8; k++) { a+=s0[k]; cI+=s2[k]; dS+=s3[k]; f+=s4[k]; }
        atomicAdd(&g_msum[c],  a);
        atomicAdd(&g_inter[c], cI);
        atomicAdd(&g_ssum[c],  dS);
        atomicAdd(&g_fg[c], (unsigned long long)f);
        __threadfence();
        is_last = (atomicAdd(&g_cnt_main, 1u) == (unsigned)(BPC_M * R - 1));
    }
    __syncthreads();
    if (!is_last) return;

    // ---- globally-last block: combine to scalar ----
    if (tid == 0) {
        double mse_sum = 0.0, dice_sum = 0.0;
        int nmask = 0;
        for (int ch = 0; ch < R; ch++) {
            double fgc = (double)__ldcg(&g_fg[ch]);
            // fg >= 1 always (thr is a bin center strictly below channel max)
            mse_sum += __ldcg(&g_msum[ch]) / (fgc + 1e-6);
            dice_sum += 1.0 - 2.0 * __ldcg(&g_inter[ch]) /
                                    (__ldcg(&g_ssum[ch]) + fgc + 1e-6);
            nmask++;
        }
        double masked_mse = mse_sum / (double)R;
        double dice = (nmask > 0) ? dice_sum / (double)nmask : 0.0;
        out[0] = (float)(0.5 * masked_mse + 0.5 * dice);
    }
    __syncthreads();   // combine reads done before reset below

    // ---- self-clean scratch back to static-init state for next replay ----
    for (int i = tid; i < R * NBINS; i += TPB)
        ((unsigned int*)g_hist)[i] = 0u;
    if (tid < R) {
        g_minkey[tid] = 0xFFFFFFFFu;
        g_maxkey[tid] = 0u;
        g_msum[tid] = 0.0; g_inter[tid] = 0.0; g_ssum[tid] = 0.0;
        g_fg[tid] = 0ull;
        g_thr[tid] = 0.0f;
        g_cnt_hist[tid] = 0u;
    }
    if (tid == R) g_cnt_main = 0u;
}

// ---------------- launch ----------------
extern "C" void kernel_launch(void* const* d_in, const int* in_sizes, int n_in,
                              void* d_out, int out_size) {
    const float4* pred = (const float4*)d_in[0];
    const float4* tgt  = (const float4*)d_in[1];
    float* out = (float*)d_out;

    k_minmax<<<dim3(BPC_MM, R), TPB>>>(tgt);
    k_hist  <<<dim3(BPC_H,  R), TPB>>>(tgt);
    k_main  <<<dim3(BPC_M,  R), TPB>>>(pred, tgt, out);
}